// round 12
// baseline (speedup 1.0000x reference)
#include <cuda_runtime.h>
#include <cstdint>

#define N_NODES 100000
#define N_EDGES 1600000
#define D_EDGE  50
#define SLOTS   64   // fixed eid slots per node (max binomial degree ~40)

// 1 if receivers buffer really holds int64, 0 if int32 (harness downcasts).
__device__ int g_idx_is_i64;

__device__ int g_cnt[N_NODES];                   // per-node degree
__device__ int g_slot[(size_t)N_NODES * SLOTS];  // eids grouped by receiver (25.6MB)
__device__ int g_ovf_n;                          // overflow count (expected 0)
__device__ int g_ovf[N_EDGES];                   // overflow eids (full-capacity safe)

__device__ __forceinline__ long long load_recv(const void* __restrict__ recv, int e) {
    return g_idx_is_i64 ? ((const long long*)recv)[e]
                        : (long long)((const int*)recv)[e];
}

// ---------------------------------------------------------------------------
// Kernel 1: init. Block 0 detects receivers dtype (first 2048 words as int64:
// true int64 indices all in [0,N_NODES); packed int32 pairs blow the range).
// All blocks zero the counters. Output needs no zeroing (gather writes it).
// ---------------------------------------------------------------------------
__global__ void init_kernel(const void* __restrict__ recv) {
    if (blockIdx.x == 0) {
        const long long* p64 = (const long long*)recv;
        int bad = 0;
        for (int i = threadIdx.x; i < 2048; i += blockDim.x) {
            long long v = p64[i];
            if (v < 0 || v >= N_NODES) bad = 1;
        }
        int any_bad = __syncthreads_or(bad);
        if (threadIdx.x == 0) { g_idx_is_i64 = any_bad ? 0 : 1; g_ovf_n = 0; }
    }
    for (int i = blockIdx.x * blockDim.x + threadIdx.x; i < N_NODES;
         i += gridDim.x * blockDim.x) {
        g_cnt[i] = 0;
    }
}

// ---------------------------------------------------------------------------
// Kernel 2: build slot lists. One pass, no scan: pos = atomicAdd(cnt[r]);
// overflow beyond SLOTS goes to a correctness-safe list (expected empty).
// ---------------------------------------------------------------------------
__global__ void build_kernel(const void* __restrict__ recv) {
    int e = blockIdx.x * blockDim.x + threadIdx.x;
    if (e >= N_EDGES) return;
    long long r = load_recv(recv, e);
    if ((unsigned long long)r >= (unsigned long long)N_NODES) return;
    int pos = atomicAdd(&g_cnt[(int)r], 1);
    if (pos < SLOTS) {
        g_slot[(size_t)r * SLOTS + pos] = e;
    } else {
        int o = atomicAdd(&g_ovf_n, 1);
        g_ovf[o] = e;
    }
}

// ---------------------------------------------------------------------------
// Kernel 3: gather. One warp per node. Lanes 0..24 own float2 dim-pairs.
// The warp preloads its 64-slot line into 2 registers (coalesced), broadcasts
// eids via shfl, and 4-way unrolls the edge loop (MLP ~100 float2/warp).
// Row reads: 25 lanes x 8B contiguous = 200B (2 lines). Writes every output
// row exactly once (zeros for empty nodes) -> no separate zero pass.
// ---------------------------------------------------------------------------
__global__ void gather_kernel(const float* __restrict__ edges,
                              float* __restrict__ out) {
    const int warp = (blockIdx.x * blockDim.x + threadIdx.x) >> 5;
    const int lane = threadIdx.x & 31;
    if (warp >= N_NODES) return;

    int cnt = g_cnt[warp];
    if (cnt > SLOTS) cnt = SLOTS;

    const int* slots = g_slot + (size_t)warp * SLOTS;
    const int e_lo = (lane < cnt) ? slots[lane] : 0;
    const int e_hi = (32 + lane < cnt) ? slots[32 + lane] : 0;

    const bool act = (lane < 25);
    const int d = 2 * lane;

    float2 a0 = make_float2(0.f, 0.f), a1 = make_float2(0.f, 0.f);
    float2 a2 = make_float2(0.f, 0.f), a3 = make_float2(0.f, 0.f);

    int j = 0;
    for (; j + 4 <= cnt; j += 4) {
        int e0 = __shfl_sync(0xffffffffu, (j + 0 < 32) ? e_lo : e_hi, (j + 0) & 31);
        int e1 = __shfl_sync(0xffffffffu, (j + 1 < 32) ? e_lo : e_hi, (j + 1) & 31);
        int e2 = __shfl_sync(0xffffffffu, (j + 2 < 32) ? e_lo : e_hi, (j + 2) & 31);
        int e3 = __shfl_sync(0xffffffffu, (j + 3 < 32) ? e_lo : e_hi, (j + 3) & 31);
        if (act) {
            float2 v0 = *reinterpret_cast<const float2*>(edges + (size_t)e0 * D_EDGE + d);
            float2 v1 = *reinterpret_cast<const float2*>(edges + (size_t)e1 * D_EDGE + d);
            float2 v2 = *reinterpret_cast<const float2*>(edges + (size_t)e2 * D_EDGE + d);
            float2 v3 = *reinterpret_cast<const float2*>(edges + (size_t)e3 * D_EDGE + d);
            a0.x += v0.x; a0.y += v0.y;
            a1.x += v1.x; a1.y += v1.y;
            a2.x += v2.x; a2.y += v2.y;
            a3.x += v3.x; a3.y += v3.y;
        }
    }
    for (; j < cnt; j++) {
        int e = __shfl_sync(0xffffffffu, (j < 32) ? e_lo : e_hi, j & 31);
        if (act) {
            float2 v = *reinterpret_cast<const float2*>(edges + (size_t)e * D_EDGE + d);
            a0.x += v.x; a0.y += v.y;
        }
    }

    if (act) {
        float2 r = make_float2((a0.x + a1.x) + (a2.x + a3.x),
                               (a0.y + a1.y) + (a2.y + a3.y));
        *reinterpret_cast<float2*>(out + (size_t)warp * D_EDGE + d) = r;
    }
}

// ---------------------------------------------------------------------------
// Kernel 4: overflow fixup (expected 0 iterations). Runs AFTER gather so the
// adds land on finalized rows. One (edge,dim) pair per thread via red.add.
// ---------------------------------------------------------------------------
__global__ void overflow_kernel(const float* __restrict__ edges,
                                const void* __restrict__ recv,
                                float* __restrict__ out) {
    const int n = g_ovf_n * D_EDGE;
    for (int i = blockIdx.x * blockDim.x + threadIdx.x; i < n;
         i += gridDim.x * blockDim.x) {
        const int o = i / D_EDGE;
        const int k = i - o * D_EDGE;
        const int e = g_ovf[o];
        long long r = load_recv(recv, e);
        if ((unsigned long long)r >= (unsigned long long)N_NODES) continue;
        float v = edges[(size_t)e * D_EDGE + k];
        asm volatile("red.global.add.f32 [%0], %1;"
                     :: "l"(out + (size_t)r * D_EDGE + k), "f"(v) : "memory");
    }
}

extern "C" void kernel_launch(void* const* d_in, const int* in_sizes, int n_in,
                              void* d_out, int out_size) {
    // Identify inputs by element count (robust to ordering):
    //   nodes: 800,000 f32 (unused) | edges: 80,000,000 f32 | receivers: 1,600,000
    const float* edges = nullptr;
    const void* receivers = nullptr;
    for (int i = 0; i < n_in; i++) {
        if (in_sizes[i] == N_EDGES * D_EDGE) {
            edges = (const float*)d_in[i];
        } else if (in_sizes[i] == N_EDGES) {
            receivers = d_in[i];
        }
    }
    float* out = (float*)d_out;

    const int T = 256;

    // 1) detect dtype + zero counters
    init_kernel<<<392, T>>>(receivers);

    // 2) build per-node slot lists (one pass, no scan)
    build_kernel<<<(N_EDGES + T - 1) / T, T>>>(receivers);

    // 3) gather: one warp per node, register accumulation
    gather_kernel<<<(N_NODES * 32 + T - 1) / T, T>>>(edges, out);

    // 4) overflow fixup (no-op for this dataset, correctness-safe in general)
    overflow_kernel<<<64, T>>>(edges, receivers, out);
}